// round 2
// baseline (speedup 1.0000x reference)
#include <cuda_runtime.h>
#include <cuda_fp16.h>
#include <stdint.h>

#define NS 32
#define TT 2048
#define ND 1024
#define GRID 64
#define NTHREADS 256
#define NWARPS 8
#define KTILES 8     // eight 16-wide k-tiles per warp (8 warps * 8 * 16 = 1024 = K)
#define ROWBLK 32    // rows of A (output neurons) per CTA
#define SBLK 16      // samples per CTA

#define ALPHA 0.1f
#define BETA  0.9f

// Double-buffered fp16 copy of the hidden state, stored in a pre-swizzled
// mma-B-fragment layout (per sample: per 16-k block, halves ordered
// [2t,2t+1,2t+8,2t+9] for t=0..3 so one 8B load yields b0||b1).
__device__ __align__(16) __half g_hbuf[2][NS * ND];
__device__ unsigned g_bar_count;
__device__ unsigned g_bar_gen;

__device__ __forceinline__ void grid_barrier() {
    __syncthreads();
    if (threadIdx.x == 0) {
        unsigned gen = *((volatile unsigned*)&g_bar_gen);
        __threadfence();
        unsigned old = atomicAdd(&g_bar_count, 1u);
        if (old == GRID - 1) {
            g_bar_count = 0;
            __threadfence();
            atomicExch(&g_bar_gen, gen + 1u);
        } else {
            while (*((volatile unsigned*)&g_bar_gen) == gen) { }
        }
        __threadfence();
    }
    __syncthreads();
}

__device__ __forceinline__ void mma16816(float* d, const uint32_t* a,
                                         uint32_t b0, uint32_t b1) {
    asm volatile(
        "mma.sync.aligned.m16n8k16.row.col.f32.f16.f16.f32 "
        "{%0,%1,%2,%3}, {%4,%5,%6,%7}, {%8,%9}, {%0,%1,%2,%3};\n"
        : "+f"(d[0]), "+f"(d[1]), "+f"(d[2]), "+f"(d[3])
        : "r"(a[0]), "r"(a[1]), "r"(a[2]), "r"(a[3]), "r"(b0), "r"(b1));
}

// Position of logical element j inside the swizzled per-sample layout.
// block = j>>4; within block r=j&15: tig=(r&7)>>1, off=((r>>3)<<1)|(r&1)
__device__ __forceinline__ int hpos(int j) {
    int r = j & 15;
    return (j & ~15) + ((r & 6) << 1) + ((r >> 3) << 1) + (r & 1);
}

__global__ __launch_bounds__(NTHREADS, 1) void rnn_kernel(
    const float* __restrict__ inp,   // [NS, TT, ND]
    const float* __restrict__ A,     // [ND, ND]
    const float* __restrict__ h0,    // [NS, ND]
    float* __restrict__ out)         // [NS, TT, ND]
{
    __shared__ float psum[NWARPS][SBLK * ROWBLK];  // 16 KB

    const int tid  = threadIdx.x;
    const int w    = tid >> 5;
    const int lane = tid & 31;
    const int g    = lane >> 2;   // groupID
    const int tig  = lane & 3;    // threadID in group

    const int cta  = blockIdx.x;
    const int rb   = cta >> 1;    // 32 row blocks
    const int sb   = cta & 1;     // 2 sample blocks
    const int row0 = rb * ROWBLK;
    const int s0   = sb * SBLK;

    // ---- Load this CTA's A-slice as resident fp16 mma fragments ----
    uint32_t afrag[KTILES][2][4];
#pragma unroll
    for (int kt = 0; kt < KTILES; kt++) {
        int k0 = (w * KTILES + kt) * 16 + 2 * tig;
#pragma unroll
        for (int m = 0; m < 2; m++) {
            const float* p = A + (size_t)(row0 + m * 16 + g) * ND + k0;
            float2 v0 = *(const float2*)(p);
            float2 v1 = *(const float2*)(p + 8 * (size_t)ND);
            float2 v2 = *(const float2*)(p + 8);
            float2 v3 = *(const float2*)(p + 8 * (size_t)ND + 8);
            __half2 q0 = __floats2half2_rn(v0.x, v0.y);
            __half2 q1 = __floats2half2_rn(v1.x, v1.y);
            __half2 q2 = __floats2half2_rn(v2.x, v2.y);
            __half2 q3 = __floats2half2_rn(v3.x, v3.y);
            afrag[kt][m][0] = *(uint32_t*)&q0;
            afrag[kt][m][1] = *(uint32_t*)&q1;
            afrag[kt][m][2] = *(uint32_t*)&q2;
            afrag[kt][m][3] = *(uint32_t*)&q3;
        }
    }

    // ---- Per-thread state ownership: (sample s_l, rows i_l, i_l+1) ----
    const int s_l  = tid >> 4;            // 0..15
    const int i_l  = (tid & 15) << 1;     // 0,2,...,30
    const int s_gl = s0 + s_l;
    const int i_gl = row0 + i_l;
    const int e    = s_l * ROWBLK + i_l;

    // init: h_0
    float2 hprev = *(const float2*)(h0 + (size_t)s_gl * ND + i_gl);
    *(float2*)(out + (size_t)s_gl * TT * ND + i_gl) = hprev;
    {
        __half2 hh = __floats2half2_rn(hprev.x, hprev.y);
        *(__half2*)&g_hbuf[0][s_gl * ND + hpos(i_gl)] = hh;
    }

    grid_barrier();

    for (int t = 1; t < TT; t++) {
        const __half* hb = g_hbuf[(t - 1) & 1];

        float d[2][2][4];
#pragma unroll
        for (int m = 0; m < 2; m++)
#pragma unroll
            for (int nu = 0; nu < 2; nu++)
#pragma unroll
                for (int c = 0; c < 4; c++) d[m][nu][c] = 0.0f;

        // ---- GEMM slice: D[i,s] = sum_k A[i,k] * h[s,k] ----
#pragma unroll
        for (int kt = 0; kt < KTILES; kt++) {
            int koff = (w * KTILES + kt) * 16 + tig * 4;
#pragma unroll
            for (int nu = 0; nu < 2; nu++) {
                int s = s0 + nu * 8 + g;
                uint2 b = *(const uint2*)(hb + (size_t)s * ND + koff);
                mma16816(d[0][nu], afrag[kt][0], b.x, b.y);
                mma16816(d[1][nu], afrag[kt][1], b.x, b.y);
            }
        }

        // ---- cross-warp reduction through SMEM ----
#pragma unroll
        for (int m = 0; m < 2; m++)
#pragma unroll
            for (int nu = 0; nu < 2; nu++)
#pragma unroll
                for (int c = 0; c < 4; c++) {
                    int i_loc = m * 16 + g + ((c >> 1) << 3);
                    int s_loc = nu * 8 + tig * 2 + (c & 1);
                    psum[w][s_loc * ROWBLK + i_loc] = d[m][nu][c];
                }
        __syncthreads();

        float sum0 = 0.0f, sum1 = 0.0f;
#pragma unroll
        for (int ww = 0; ww < NWARPS; ww++) {
            float2 p = *(const float2*)&psum[ww][e];
            sum0 += p.x; sum1 += p.y;
        }

        float2 x = *(const float2*)(inp + (size_t)s_gl * TT * ND +
                                    (size_t)(t - 1) * ND + i_gl);
        float hn0 = BETA * hprev.x + ALPHA * (sum0 + x.x);
        float hn1 = BETA * hprev.y + ALPHA * (sum1 + x.y);
        hprev.x = hn0; hprev.y = hn1;

        *(float2*)(out + (size_t)s_gl * TT * ND + (size_t)t * ND + i_gl) =
            make_float2(hn0, hn1);
        __half2 hh = __floats2half2_rn(hn0, hn1);
        *(__half2*)&g_hbuf[t & 1][s_gl * ND + hpos(i_gl)] = hh;

        grid_barrier();
    }
}

extern "C" void kernel_launch(void* const* d_in, const int* in_sizes, int n_in,
                              void* d_out, int out_size) {
    const float* inp = (const float*)d_in[0];
    const float* A   = (const float*)d_in[1];
    const float* h0  = (const float*)d_in[2];
    float* out       = (float*)d_out;
    rnn_kernel<<<GRID, NTHREADS>>>(inp, A, h0, out);
}